// round 17
// baseline (speedup 1.0000x reference)
#include <cuda_runtime.h>
#include <cuda_fp16.h>
#include <cstdint>

#define NB 2
#define NS 256
#define NE 512
#define NH 8
#define NDH 64
#define NTC 768
#define NL 8192
#define NOLD 6144
#define FSPLIT 8
#define FKT 128
#define NCH2 (NL/FKT/FSPLIT)   // 8 chunks per flash block

// Scratch. K/V stored CHUNK-CONTIGUOUS and PRE-SWIZZLED (SW128).
__device__ __align__(128) __half g_q[NB*NS*NE];   // scaled by 0.125*log2e
__device__ __align__(128) __half g_k[NB*NL*NDH];
__device__ __align__(128) __half g_v[NB*NDH*NL];
__device__ __half g_attn_h[NB*NS*NE];
__device__ float  g_po[FSPLIT*NB*NS*NE];
__device__ float  g_pl[FSPLIT*NB*NH*NS];

#define SWZ(o) ((o) ^ (((o) >> 3) & 0x70))

// ---------------------------------------------------------------------------
__device__ __forceinline__ void mma_f16(float c[4], const uint32_t a[4],
                                        const uint32_t b[2]) {
    asm volatile(
        "mma.sync.aligned.m16n8k16.row.col.f32.f16.f16.f32 "
        "{%0,%1,%2,%3}, {%4,%5,%6,%7}, {%8,%9}, {%0,%1,%2,%3};"
        : "+f"(c[0]), "+f"(c[1]), "+f"(c[2]), "+f"(c[3])
        : "r"(a[0]), "r"(a[1]), "r"(a[2]), "r"(a[3]), "r"(b[0]), "r"(b[1]));
}
__device__ __forceinline__ uint32_t packh2(float x, float y) {
    __half2 h = __floats2half2_rn(x, y);
    return *(uint32_t*)&h;
}
__device__ __forceinline__ float ex2f(float x) {
    float r;
    asm("ex2.approx.f32 %0, %1;" : "=f"(r) : "f"(x));
    return r;
}
__device__ __forceinline__ void ldsm4(uint32_t r[4], uint32_t a) {
    asm volatile("ldmatrix.sync.aligned.m8n8.x4.shared.b16 {%0,%1,%2,%3}, [%4];"
                 : "=r"(r[0]), "=r"(r[1]), "=r"(r[2]), "=r"(r[3]) : "r"(a));
}
#define MBAR_INIT(mb, c) \
    asm volatile("mbarrier.init.shared.b64 [%0], %1;" :: "r"(mb), "r"(c) : "memory")
#define EXPECT_TX(mb, n) \
    asm volatile("mbarrier.arrive.expect_tx.shared.b64 _, [%0], %1;" \
                 :: "r"(mb), "r"(n) : "memory")
#define BULK16K(dst, src, mb) \
    asm volatile("cp.async.bulk.shared::cluster.global.mbarrier::complete_tx::bytes " \
                 "[%0], [%1], 16384, [%2];" :: "r"(dst), "l"(src), "r"(mb) : "memory")
__device__ __forceinline__ void mbar_wait(uint32_t mb, uint32_t parity) {
    asm volatile(
        "{\n\t.reg .pred P;\n\t"
        "W_%=:\n\t"
        "mbarrier.try_wait.parity.acquire.cta.shared::cta.b64 P, [%0], %1, 0x989680;\n\t"
        "@!P bra W_%=;\n\t}"
        :: "r"(mb), "r"(parity) : "memory");
}

// ---------------------------------------------------------------------------
// fp16 GEMM core (32x64 tile) for QKV: K=512 in 32-k slabs, double buffered.
// ---------------------------------------------------------------------------
#define HSTR 40
#define AH_ST (32*HSTR)
#define WH_ST (64*HSTR)

__device__ __forceinline__ void gemm_f16_core(
    const float* __restrict__ A, const float* __restrict__ W,
    int m0, int n0, __half* Ah, __half* Wh, float acc[2][4])
{
    const int t = threadIdx.x;
    const int lane = t & 31, g = lane >> 2, tg = lane & 3;
    const int warp = t >> 5, wm = warp >> 2, wn = warp & 3;
    const int arow = t >> 3, acol = (t & 7) * 4;
    const int wrow = t >> 2, wcol = (t & 3) * 8;

#pragma unroll
    for (int nt = 0; nt < 2; nt++)
#pragma unroll
        for (int i = 0; i < 4; i++) acc[nt][i] = 0.f;

    uint2 ra;
    {
        float4 af = *(const float4*)(A + (size_t)(m0+arow)*NE + acol);
        ra.x = packh2(af.x, af.y); ra.y = packh2(af.z, af.w);
    }
    float4 rw0 = *(const float4*)(W + (size_t)(n0+wrow)*NE + wcol);
    float4 rw1 = *(const float4*)(W + (size_t)(n0+wrow)*NE + wcol + 4);
    {
        *(uint2*)&Ah[arow*HSTR + acol] = ra;
        uint4 wv;
        wv.x = packh2(rw0.x, rw0.y); wv.y = packh2(rw0.z, rw0.w);
        wv.z = packh2(rw1.x, rw1.y); wv.w = packh2(rw1.z, rw1.w);
        *(uint4*)&Wh[wrow*HSTR + wcol] = wv;
    }
    __syncthreads();

    for (int s = 0; s < 16; s++) {
        int p = s & 1;
        if (s < 15) {
            int k0 = (s+1)*32;
            float4 af = *(const float4*)(A + (size_t)(m0+arow)*NE + k0 + acol);
            ra.x = packh2(af.x, af.y); ra.y = packh2(af.z, af.w);
            rw0 = *(const float4*)(W + (size_t)(n0+wrow)*NE + k0 + wcol);
            rw1 = *(const float4*)(W + (size_t)(n0+wrow)*NE + k0 + wcol + 4);
        }
        const __half* Ap = Ah + p*AH_ST;
        const __half* Wp = Wh + p*WH_ST;
#pragma unroll
        for (int kt = 0; kt < 2; kt++) {
            uint32_t a[4];
            const __half* ab = Ap + (wm*16)*HSTR + kt*16;
            a[0] = *(const uint32_t*)&ab[g*HSTR + 2*tg];
            a[1] = *(const uint32_t*)&ab[(g+8)*HSTR + 2*tg];
            a[2] = *(const uint32_t*)&ab[g*HSTR + 2*tg + 8];
            a[3] = *(const uint32_t*)&ab[(g+8)*HSTR + 2*tg + 8];
#pragma unroll
            for (int nt = 0; nt < 2; nt++) {
                const __half* wb = Wp + (wn*16 + nt*8 + g)*HSTR + kt*16;
                uint32_t bb[2];
                bb[0] = *(const uint32_t*)&wb[2*tg];
                bb[1] = *(const uint32_t*)&wb[2*tg + 8];
                mma_f16(acc[nt], a, bb);
            }
        }
        if (s < 15) {
            *(uint2*)&Ah[(1-p)*AH_ST + arow*HSTR + acol] = ra;
            uint4 wv;
            wv.x = packh2(rw0.x, rw0.y); wv.y = packh2(rw0.z, rw0.w);
            wv.z = packh2(rw1.x, rw1.y); wv.w = packh2(rw1.z, rw1.w);
            *(uint4*)&Wh[(1-p)*WH_ST + wrow*HSTR + wcol] = wv;
        }
        __syncthreads();
    }
}

// ---------------------------------------------------------------------------
// Fused prologue kernel: blocks 0..383 = QKV projections; 384..575 = cache
// copy (fp32->fp16 + chunked/swizzled K and transposed V).
// ---------------------------------------------------------------------------
__global__ __launch_bounds__(256) void pre_kernel(
    const float* __restrict__ x,
    const float4* __restrict__ kc, const float4* __restrict__ vc,
    const float* __restrict__ Wq, const float* __restrict__ bq,
    const float* __restrict__ Wk, const float* __restrict__ bk,
    const float* __restrict__ Wv, const float* __restrict__ bv)
{
    __shared__ __half sm[2*AH_ST + 2*WH_ST];
    const int bx = blockIdx.x;
    const int t = threadIdx.x;

    if (bx < 384) {
        const int mode = bx >> 7;
        const int r = bx & 127;
        const int m0 = (r >> 3) * 32, n0 = (r & 7) * 64;
        const float* W    = (mode == 0) ? Wq : ((mode == 1) ? Wk : Wv);
        const float* bias = (mode == 0) ? bq : ((mode == 1) ? bk : bv);
        __half* Ah = sm;
        __half* Wh = sm + 2*AH_ST;

        float acc[2][4];
        gemm_f16_core(x, W, m0, n0, Ah, Wh, acc);

        const int lane = t & 31, g = lane >> 2, tg = lane & 3;
        const int warp = t >> 5, wm = warp >> 2, wn = warp & 3;
        const float QSCALE = 0.125f * 1.44269504088896f;
#pragma unroll
        for (int nt = 0; nt < 2; nt++) {
#pragma unroll
            for (int i = 0; i < 4; i++) {
                int m = m0 + wm*16 + g + (i >= 2 ? 8 : 0);
                int n = n0 + wn*16 + nt*8 + 2*tg + (i & 1);
                float v = acc[nt][i] + bias[n];
                int b = m >> 8, s = m & 255;
                int d = n & 63;
                int l = NOLD + s*NH + (n >> 6);
                if (mode == 0) {
                    g_q[m*NE + n] = __float2half_rn(v * QSCALE);
                } else if (mode == 1) {
                    char* kb = (char*)g_k + (size_t)b*NL*128 + (size_t)(l>>7)*16384;
                    uint32_t off = (uint32_t)((l&127)*128 + d*2);
                    *(__half*)(kb + SWZ(off)) = __float2half_rn(v);
                } else {
                    char* vb = (char*)g_v + (size_t)b*NL*128 + (size_t)(l>>7)*16384
                             + ((l>>6)&1)*8192;
                    uint32_t off = (uint32_t)(d*128 + (l&63)*2);
                    *(__half*)(vb + SWZ(off)) = __float2half_rn(v);
                }
            }
        }
    } else {
        __half* sh = sm;
        const int cb = bx - 384;
        const int b = cb / 96, l0 = (cb % 96) * 64;
        const int lr = t >> 2;
        const int l = l0 + lr;
        const float4* krow = kc + ((size_t)(b*NOLD + l)*64 + (t&3)*16)/4;
        const float4* vrow = vc + ((size_t)(b*NOLD + l)*64 + (t&3)*16)/4;

        {
            uint4 h0, h1;
            float4 k0 = krow[0], k1 = krow[1], k2 = krow[2], k3 = krow[3];
            h0.x = packh2(k0.x, k0.y); h0.y = packh2(k0.z, k0.w);
            h0.z = packh2(k1.x, k1.y); h0.w = packh2(k1.z, k1.w);
            h1.x = packh2(k2.x, k2.y); h1.y = packh2(k2.z, k2.w);
            h1.z = packh2(k3.x, k3.y); h1.w = packh2(k3.z, k3.w);
            char* kb = (char*)g_k + (size_t)b*NL*128 + (size_t)(l>>7)*16384;
            uint32_t off = (uint32_t)((l&127)*128 + (t&3)*32);
            *(uint4*)(kb + SWZ(off))      = h0;
            *(uint4*)(kb + SWZ(off + 16)) = h1;
        }
        {
            float4 v0 = vrow[0], v1 = vrow[1], v2 = vrow[2], v3 = vrow[3];
            uint32_t* sd = (uint32_t*)&sh[lr*68 + (t&3)*16];
            sd[0] = packh2(v0.x, v0.y); sd[1] = packh2(v0.z, v0.w);
            sd[2] = packh2(v1.x, v1.y); sd[3] = packh2(v1.z, v1.w);
            sd[4] = packh2(v2.x, v2.y); sd[5] = packh2(v2.z, v2.w);
            sd[6] = packh2(v3.x, v3.y); sd[7] = packh2(v3.z, v3.w);
        }
        __syncthreads();
        {
            const int d = t >> 2, q = t & 3;
            uint4 A, B;
            uint32_t ob[8];
#pragma unroll
            for (int j = 0; j < 8; j++) {
                __half2 hh = __halves2half2(sh[(q*16+2*j)*68 + d],
                                            sh[(q*16+2*j+1)*68 + d]);
                ob[j] = *(uint32_t*)&hh;
            }
            A.x = ob[0]; A.y = ob[1]; A.z = ob[2]; A.w = ob[3];
            B.x = ob[4]; B.y = ob[5]; B.z = ob[6]; B.w = ob[7];
            char* vb = (char*)g_v + (size_t)b*NL*128 + (size_t)(l0>>7)*16384
                     + ((l0>>6)&1)*8192;
            uint32_t off = (uint32_t)(d*128 + q*32);
            *(uint4*)(vb + SWZ(off))      = A;
            *(uint4*)(vb + SWZ(off + 16)) = B;
        }
    }
}

// ---------------------------------------------------------------------------
// Output projection: 32x32 tiles, grid 256 blocks (2x parallelism vs R16).
// 8 warps = 2m x 4n; warp tile 16m x 8n; 2 HMMA per warp per 32-k slab.
// ---------------------------------------------------------------------------
#define OST 40
#define OA_ST (32*OST)

__global__ __launch_bounds__(256) void out_tc_kernel(
    const float* __restrict__ Wo, const float* __restrict__ bo,
    float* __restrict__ out)
{
    __shared__ __half Ah[2*OA_ST];
    __shared__ __half Wh[2*OA_ST];
    const int t = threadIdx.x;
    const int lane = t & 31, g = lane >> 2, tg = lane & 3;
    const int warp = t >> 5, wm = warp >> 2, wn = warp & 3;
    const int m0 = blockIdx.y*32, n0 = blockIdx.x*32;
    const int row = t >> 3, col = (t & 7) * 4;   // staging: 32 rows x 32 elems

    float acc[4] = {0.f, 0.f, 0.f, 0.f};

    // preload slab 0
    uint2 ra = *(const uint2*)(g_attn_h + (size_t)(m0+row)*NE + col);
    float4 wf = *(const float4*)(Wo + (size_t)(n0+row)*NE + col);
    {
        *(uint2*)&Ah[row*OST + col] = ra;
        uint2 wv;
        wv.x = packh2(wf.x, wf.y); wv.y = packh2(wf.z, wf.w);
        *(uint2*)&Wh[row*OST + col] = wv;
    }
    __syncthreads();

    for (int s = 0; s < 16; s++) {
        int p = s & 1;
        if (s < 15) {
            int k0 = (s+1)*32;
            ra = *(const uint2*)(g_attn_h + (size_t)(m0+row)*NE + k0 + col);
            wf = *(const float4*)(Wo + (size_t)(n0+row)*NE + k0 + col);
        }
        const __half* Ap = Ah + p*OA_ST;
        const __half* Wp = Wh + p*OA_ST;
#pragma unroll
        for (int kt = 0; kt < 2; kt++) {
            uint32_t a[4];
            const __half* ab = Ap + (wm*16)*OST + kt*16;
            a[0] = *(const uint32_t*)&ab[g*OST + 2*tg];
            a[1] = *(const uint32_t*)&ab[(g+8)*OST + 2*tg];
            a[2] = *(const uint32_t*)&ab[g*OST + 2*tg + 8];
            a[3] = *(const uint32_t*)&ab[(g+8)*OST + 2*tg + 8];
            const __half* wb = Wp + (wn*8 + g)*OST + kt*16;
            uint32_t bb[2];
            bb[0] = *(const uint32_t*)&wb[2*tg];
            bb[1] = *(const uint32_t*)&wb[2*tg + 8];
            mma_f16(acc, a, bb);
        }
        if (s < 15) {
            *(uint2*)&Ah[(1-p)*OA_ST + row*OST + col] = ra;
            uint2 wv;
            wv.x = packh2(wf.x, wf.y); wv.y = packh2(wf.z, wf.w);
            *(uint2*)&Wh[(1-p)*OA_ST + row*OST + col] = wv;
        }
        __syncthreads();
    }

    {
        int r0 = m0 + wm*16 + g;
        int c  = n0 + wn*8 + 2*tg;
        *(float2*)(out + (size_t)r0*NE + c) =
            make_float2(acc[0] + bo[c], acc[1] + bo[c+1]);
        *(float2*)(out + (size_t)(r0+8)*NE + c) =
            make_float2(acc[2] + bo[c], acc[3] + bo[c+1]);
    }
}

// ---------------------------------------------------------------------------
// fp16 flash, MT=128 (16 seq x 8 heads), cp.async.bulk chunk staging.
// ---------------------------------------------------------------------------
#define FLASH_SMEM (65536 + 1024 + 64)

__global__ __launch_bounds__(256, 2) void flash_f16_kernel()
{
    extern __shared__ __align__(16) char smraw[];
    uint32_t sb = (uint32_t)__cvta_generic_to_shared(smraw);
    uint32_t ab = (sb + 1023) & ~1023u;
    uint32_t mb0 = ab + 65536, mb1 = mb0 + 8;

    const int t = threadIdx.x;
    const int lane = t & 31, g = lane>>2, tg = lane&3;
    const int warp = t>>5;
    const int by = blockIdx.y, b = by>>3, lh = by&7;
    const int s0 = blockIdx.x*16;
    const int c0 = lh*NCH2;

    const char* kgb = (const char*)g_k + (size_t)b*NL*128;
    const char* vgb = (const char*)g_v + (size_t)b*NL*128;

    if (t == 0) { MBAR_INIT(mb0, 1); MBAR_INIT(mb1, 1); }
    __syncthreads();
    if (t == 0) {
        EXPECT_TX(mb0, 32768);
        BULK16K(ab,         kgb + (size_t)c0*16384, mb0);
        BULK16K(ab + 32768, vgb + (size_t)c0*16384, mb0);
        EXPECT_TX(mb1, 32768);
        BULK16K(ab + 16384, kgb + (size_t)(c0+1)*16384, mb1);
        BULK16K(ab + 49152, vgb + (size_t)(c0+1)*16384, mb1);
    }

    uint32_t qa[4][4];
    {
        const __half* qb = g_q + (size_t)(b*NS + s0)*NE + warp*16*64;
#pragma unroll
        for (int kt = 0; kt < 4; kt++) {
            qa[kt][0] = *(const uint32_t*)&qb[(size_t)g*64     + kt*16 + 2*tg];
            qa[kt][1] = *(const uint32_t*)&qb[(size_t)(g+8)*64 + kt*16 + 2*tg];
            qa[kt][2] = *(const uint32_t*)&qb[(size_t)g*64     + kt*16 + 2*tg + 8];
            qa[kt][3] = *(const uint32_t*)&qb[(size_t)(g+8)*64 + kt*16 + 2*tg + 8];
        }
    }

    const int lrow = lane & 7, lmat = lane >> 3;
    const uint32_t rbase = (uint32_t)(lrow * 128);
    const uint32_t xorm  = (uint32_t)(lrow << 4);
    const uint32_t lm16  = (uint32_t)(lmat * 16);

    float o[8][4];
#pragma unroll
    for (int nd = 0; nd < 8; nd++)
#pragma unroll
        for (int i = 0; i < 4; i++) o[nd][i] = 0.f;
    float lp0 = 0.f, lp1 = 0.f;

    for (int ch = 0; ch < NCH2; ch++) {
        const int p = ch & 1;
        const uint32_t mbp = p ? mb1 : mb0;
        mbar_wait(mbp, (uint32_t)((ch >> 1) & 1));

        const uint32_t kb = ab + p*16384;
        const uint32_t vb = ab + 32768 + p*16384;

#pragma unroll
        for (int jp = 0; jp < 4; jp++) {
            float sc[4][4];
#pragma unroll
            for (int nt = 0; nt < 4; nt++)
#pragma unroll
                for (int i = 0; i < 4; i++) sc[nt][i] = 0.f;
#pragma unroll
            for (int nt = 0; nt < 4; nt++) {
                const int ntg = jp*4 + nt;
#pragma unroll
                for (int ktp = 0; ktp < 2; ktp++) {
                    uint32_t bq[4];
                    ldsm4(bq, kb + (uint32_t)(ntg*1024) + rbase +
                              (((uint32_t)(ktp*64) | lm16) ^ xorm));
                    mma_f16(sc[nt], qa[2*ktp],   &bq[0]);
                    mma_f16(sc[nt], qa[2*ktp+1], &bq[2]);
                }
            }

            uint32_t pa[2][4];
#pragma unroll
            for (int jj = 0; jj < 2; jj++) {
                float e00 = ex2f(sc[2*jj][0]),   e01 = ex2f(sc[2*jj][1]);
                float e02 = ex2f(sc[2*jj][2]),   e03 = ex2f(sc[2*jj][3]);
                float e10 = ex2f(sc[2*jj+1][0]), e11 = ex2f(sc[2*jj+1][1]);
                float e12 = ex2f(sc[2*jj+1][2]), e13 = ex2f(sc[2*jj+1][3]);
                lp0 += e00 + e01 + e10 + e11;
                lp1 += e02 + e03 + e12 + e13;
                pa[jj][0] = packh2(e00, e01);
                pa[jj][1] = packh2(e02, e03);
                pa[jj][2] = packh2(e10, e11);
                pa[jj][3] = packh2(e12, e13);
            }

            const uint32_t hvb = vb + (uint32_t)((jp >> 1)*8192);
            const uint32_t klow = (((uint32_t)((jp & 1)*64) | lm16) ^ xorm);
#pragma unroll
            for (int nd = 0; nd < 8; nd++) {
                uint32_t bv[4];
                ldsm4(bv, hvb + (uint32_t)(nd*1024) + rbase + klow);
                mma_f16(o[nd], pa[0], &bv[0]);
                mma_f16(o[nd], pa[1], &bv[2]);
            }
        }

        __syncthreads();
        if (ch + 2 < NCH2 && t == 0) {
            EXPECT_TX(mbp, 32768);
            BULK16K(kb, kgb + (size_t)(c0+ch+2)*16384, mbp);
            BULK16K(vb, vgb + (size_t)(c0+ch+2)*16384, mbp);
        }
    }

    {
        float* po = g_po + (size_t)lh*(NB*NS*NE) + (size_t)(b*NS + s0)*NE;
        int r0 = warp*16 + g;
#pragma unroll
        for (int nd = 0; nd < 8; nd++) {
            *(float2*)&po[(size_t)r0*64 + nd*8 + 2*tg] =
                make_float2(o[nd][0], o[nd][1]);
            *(float2*)&po[(size_t)(r0+8)*64 + nd*8 + 2*tg] =
                make_float2(o[nd][2], o[nd][3]);
        }
        lp0 += __shfl_xor_sync(0xffffffffu, lp0, 1);
        lp0 += __shfl_xor_sync(0xffffffffu, lp0, 2);
        lp1 += __shfl_xor_sync(0xffffffffu, lp1, 1);
        lp1 += __shfl_xor_sync(0xffffffffu, lp1, 2);
        if (tg == 0) {
            int r = r0;
            g_pl[lh*(NB*NH*NS) + (b*NH + (r&7))*NS + s0 + (r>>3)] = lp0;
            r = r0 + 8;
            g_pl[lh*(NB*NH*NS) + (b*NH + (r&7))*NS + s0 + (r>>3)] = lp1;
        }
    }
}

// ---------------------------------------------------------------------------
// Merge 8 partials, 2 outputs per thread for ILP.
// ---------------------------------------------------------------------------
__global__ __launch_bounds__(256) void merge_kernel()
{
    int i0 = (blockIdx.x*blockDim.x + threadIdx.x)*2;
    if (i0 >= NB*NS*NE/4) return;
    float4 acc[2];
    float  inv[2];
#pragma unroll
    for (int u = 0; u < 2; u++) {
        int i = i0 + u;
        int h  = (i >> 4) & 7;
        int q  = (i >> 7) & 255;
        int b  = i >> 15;
        int rml = (b*NH + h)*NS + q;
        float lsum = 0.f;
#pragma unroll
        for (int s = 0; s < FSPLIT; s++) lsum += g_pl[s*(NB*NH*NS) + rml];
        inv[u] = 1.f / lsum;
        acc[u] = make_float4(0.f, 0.f, 0.f, 0.f);
#pragma unroll
        for (int s = 0; s < FSPLIT; s++) {
            float4 ov = ((const float4*)(g_po + (size_t)s*NB*NS*NE))[i];
            acc[u].x += ov.x; acc[u].y += ov.y;
            acc[u].z += ov.z; acc[u].w += ov.w;
        }
    }
#pragma unroll
    for (int u = 0; u < 2; u++) {
        uint2 r;
        r.x = packh2(acc[u].x*inv[u], acc[u].y*inv[u]);
        r.y = packh2(acc[u].z*inv[u], acc[u].w*inv[u]);
        ((uint2*)g_attn_h)[i0 + u] = r;
    }
}

// ---------------------------------------------------------------------------
extern "C" void kernel_launch(void* const* d_in, const int* in_sizes, int n_in,
                              void* d_out, int out_size)
{
    const float* x  = (const float*)d_in[0];
    const float* kc = (const float*)d_in[1];
    const float* vc = (const float*)d_in[2];
    const float* Wq = (const float*)d_in[3];
    const float* bq = (const float*)d_in[4];
    const float* Wk = (const float*)d_in[5];
    const float* bk = (const float*)d_in[6];
    const float* Wv = (const float*)d_in[7];
    const float* bv = (const float*)d_in[8];
    const float* Wo = (const float*)d_in[9];
    const float* bo = (const float*)d_in[10];
    float* out = (float*)d_out;

    cudaFuncSetAttribute(flash_f16_kernel,
                         cudaFuncAttributeMaxDynamicSharedMemorySize,
                         FLASH_SMEM);

    pre_kernel<<<576, 256>>>(x, (const float4*)kc, (const float4*)vc,
                             Wq, bq, Wk, bk, Wv, bv);

    flash_f16_kernel<<<dim3(NS/16, NB*FSPLIT), 256, FLASH_SMEM>>>();

    merge_kernel<<<NB*NS*NE/8/256, 256>>>();

    out_tc_kernel<<<dim3(16, 16), 256>>>(Wo, bo, out);
}